// round 3
// baseline (speedup 1.0000x reference)
#include <cuda_runtime.h>

#define NN 50000
#define EE 800000
#define H  128
constexpr float BN_EPS = 1e-5f;
constexpr float SLOPE  = 0.01f;

// ---------------- scratch (device globals; no allocation allowed) ----------
__device__ __align__(16) float g_bufA[NN * H];
__device__ __align__(16) float g_bufB[NN * H];
__device__ __align__(16) float g_agg [NN * H];
__device__ int   g_rowptr[NN + 1];
__device__ int   g_cursor[NN];
__device__ int   g_col[EE];
__device__ float g_sum[H];
__device__ float g_sumsq[H];
__device__ float g_scale[H];
__device__ float g_shift[H];
__device__ int   g_is64;   // 1 if edge_index is int64, 0 if int32

// buffer selectors: 0 = external x, 1 = g_bufA, 2 = g_bufB
__device__ __forceinline__ const float* pick_r(const float* x, int s) {
    return (s == 0) ? x : ((s == 1) ? (const float*)g_bufA : (const float*)g_bufB);
}
__device__ __forceinline__ float* pick_w(int s) {
    return (s == 1) ? (float*)g_bufA : (float*)g_bufB;
}

// edge accessors honoring detected dtype
__device__ __forceinline__ int edge_src(const void* ei, int e) {
    if (g_is64) return (int)((const long long*)ei)[e];
    return ((const int*)ei)[e];
}
__device__ __forceinline__ int edge_dst(const void* ei, int e) {
    if (g_is64) return (int)((const long long*)ei)[EE + e];
    return ((const int*)ei)[EE + e];
}

// ---------------- dtype detection -----------------------------------------
// If data is int64, every 64-bit word is an index in [0, NN). If data is
// int32, a 64-bit read packs two random indices -> high word nonzero with
// overwhelming probability over 256 samples.
__global__ void k_detect(const void* ei) {
    __shared__ int bad;
    if (threadIdx.x == 0) bad = 0;
    __syncthreads();
    const long long* p = (const long long*)ei;
    long long v = p[threadIdx.x];
    if (v < 0 || v >= NN) atomicOr(&bad, 1);
    __syncthreads();
    if (threadIdx.x == 0) g_is64 = bad ? 0 : 1;
}

// ---------------- CSR build ------------------------------------------------
__global__ void k_zero_deg() {
    int i = blockIdx.x * blockDim.x + threadIdx.x;
    if (i < NN) g_cursor[i] = 0;
}

__global__ void k_hist(const void* __restrict__ ei) {
    int e = blockIdx.x * blockDim.x + threadIdx.x;
    if (e < EE) {
        int dst = edge_dst(ei, e);
        atomicAdd(&g_cursor[dst], 1);
    }
}

// single-block exclusive scan of degrees -> rowptr, also resets cursor=rowptr
__global__ void k_scan() {
    __shared__ int s[1024];
    int t = threadIdx.x;
    const int per = (NN + 1023) / 1024;
    int beg = t * per;
    int end = min(beg + per, NN);
    int sum = 0;
    for (int i = beg; i < end; i++) sum += g_cursor[i];
    s[t] = sum;
    __syncthreads();
    for (int off = 1; off < 1024; off <<= 1) {
        int add = (t >= off) ? s[t - off] : 0;
        __syncthreads();
        s[t] += add;
        __syncthreads();
    }
    int run = (t == 0) ? 0 : s[t - 1];
    for (int i = beg; i < end; i++) {
        int d = g_cursor[i];
        g_rowptr[i] = run;
        g_cursor[i] = run;
        run += d;
    }
    if (t == 1023) g_rowptr[NN] = run;   // == EE
}

__global__ void k_fill(const void* __restrict__ ei) {
    int e = blockIdx.x * blockDim.x + threadIdx.x;
    if (e < EE) {
        int src = edge_src(ei, e);
        int dst = edge_dst(ei, e);
        int pos = atomicAdd(&g_cursor[dst], 1);
        g_col[pos] = src;
    }
}

// ---------------- aggregation: one warp per node, float4 lanes -------------
__global__ void __launch_bounds__(256) k_agg(const float* __restrict__ x, int src) {
    int warp = threadIdx.x >> 5;
    int lane = threadIdx.x & 31;
    int node = blockIdx.x * 8 + warp;
    if (node >= NN) return;
    const float* hin = pick_r(x, src);
    int beg = g_rowptr[node];
    int end = g_rowptr[node + 1];
    const float4* in4 = (const float4*)hin;
    float4 a = make_float4(0.f, 0.f, 0.f, 0.f);
    int j = beg;
    for (; j + 3 < end; j += 4) {
        int s0 = g_col[j + 0];
        int s1 = g_col[j + 1];
        int s2 = g_col[j + 2];
        int s3 = g_col[j + 3];
        float4 v0 = in4[s0 * 32 + lane];
        float4 v1 = in4[s1 * 32 + lane];
        float4 v2 = in4[s2 * 32 + lane];
        float4 v3 = in4[s3 * 32 + lane];
        a.x += (v0.x + v1.x) + (v2.x + v3.x);
        a.y += (v0.y + v1.y) + (v2.y + v3.y);
        a.z += (v0.z + v1.z) + (v2.z + v3.z);
        a.w += (v0.w + v1.w) + (v2.w + v3.w);
    }
    for (; j < end; j++) {
        int s0 = g_col[j];
        float4 v0 = in4[s0 * 32 + lane];
        a.x += v0.x; a.y += v0.y; a.z += v0.z; a.w += v0.w;
    }
    float inv = 1.0f / (float)max(end - beg, 1);
    float4 o = make_float4(a.x * inv, a.y * inv, a.z * inv, a.w * inv);
    ((float4*)g_agg)[node * 32 + lane] = o;
}

__global__ void k_zero_stats() {
    int c = threadIdx.x;
    if (c < H) { g_sum[c] = 0.f; g_sumsq[c] = 0.f; }
}

// ---------------- fused GEMM: out = lrelu(agg@Wl + hin@Wr + b) + BN stats --
// C[50000,128] = [agg | hin] (N x 256) @ [Wl ; Wr] (256 x 128)
// BM=128, BN=128, BK=8, 256 threads, 8x8 microtile (split-half layout).
__global__ void __launch_bounds__(256, 2) k_gemm(
    const float* __restrict__ x, int src, int dst,
    const float* __restrict__ Wl,
    const float* __restrict__ Wr,
    const float* __restrict__ bias)
{
    __shared__ __align__(16) float As[2][8][128];
    __shared__ __align__(16) float Bs[2][8][128];
    __shared__ float s_sum[H];
    __shared__ float s_sumsq[H];

    const float* hin = pick_r(x, src);
    float*       out = pick_w(dst);

    const int tid  = threadIdx.x;
    const int row0 = blockIdx.x * 128;
    const int tx = tid & 15;      // column group
    const int ty = tid >> 4;      // row group

    // A loader: each thread one float4 (row lm, k offset lk4)
    const int lm  = tid >> 1;
    const int lk4 = (tid & 1) * 4;
    // B loader: row bk, float4 column bn4
    const int bk  = tid >> 5;
    const int bn4 = (tid & 31) * 4;

    float acc[8][8];
    #pragma unroll
    for (int i = 0; i < 8; i++)
        #pragma unroll
        for (int jj = 0; jj < 8; jj++) acc[i][jj] = 0.f;

    float4 ra, rb;

    // prologue: load k-tile 0
    {
        int grow = row0 + lm;
        if (grow < NN) ra = *(const float4*)&g_agg[grow * H + lk4];
        else           ra = make_float4(0.f, 0.f, 0.f, 0.f);
        rb = *(const float4*)&Wl[bk * H + bn4];
        As[0][lk4 + 0][lm] = ra.x;
        As[0][lk4 + 1][lm] = ra.y;
        As[0][lk4 + 2][lm] = ra.z;
        As[0][lk4 + 3][lm] = ra.w;
        *(float4*)&Bs[0][bk][bn4] = rb;
    }
    __syncthreads();

    for (int kt = 0; kt < 32; kt++) {
        const int cur = kt & 1;
        if (kt < 31) {
            int koff = (kt + 1) * 8;
            const float* srcA = (koff < 128) ? (const float*)g_agg : hin;
            const float* W    = (koff < 128) ? Wl : Wr;
            int o = koff & 127;
            int grow = row0 + lm;
            if (grow < NN) ra = *(const float4*)&srcA[grow * H + o + lk4];
            else           ra = make_float4(0.f, 0.f, 0.f, 0.f);
            rb = *(const float4*)&W[(o + bk) * H + bn4];
        }

        #pragma unroll
        for (int kk = 0; kk < 8; kk++) {
            float4 a0 = *(const float4*)&As[cur][kk][ty * 4];
            float4 a1 = *(const float4*)&As[cur][kk][64 + ty * 4];
            float4 b0 = *(const float4*)&Bs[cur][kk][tx * 4];
            float4 b1 = *(const float4*)&Bs[cur][kk][64 + tx * 4];
            float av[8] = {a0.x, a0.y, a0.z, a0.w, a1.x, a1.y, a1.z, a1.w};
            float bv[8] = {b0.x, b0.y, b0.z, b0.w, b1.x, b1.y, b1.z, b1.w};
            #pragma unroll
            for (int i = 0; i < 8; i++)
                #pragma unroll
                for (int jj = 0; jj < 8; jj++)
                    acc[i][jj] += av[i] * bv[jj];
        }

        if (kt < 31) {
            const int nx = cur ^ 1;
            As[nx][lk4 + 0][lm] = ra.x;
            As[nx][lk4 + 1][lm] = ra.y;
            As[nx][lk4 + 2][lm] = ra.z;
            As[nx][lk4 + 3][lm] = ra.w;
            *(float4*)&Bs[nx][bk][bn4] = rb;
        }
        __syncthreads();
    }

    // ---------------- epilogue: bias + leaky relu + store + BN partials ----
    if (tid < H) { s_sum[tid] = 0.f; s_sumsq[tid] = 0.f; }
    __syncthreads();

    int cols[8];
    #pragma unroll
    for (int jj = 0; jj < 8; jj++)
        cols[jj] = (jj < 4) ? (tx * 4 + jj) : (64 + tx * 4 + (jj - 4));
    float bvals[8];
    #pragma unroll
    for (int jj = 0; jj < 8; jj++) bvals[jj] = bias[cols[jj]];

    float csum[8], csq[8];
    #pragma unroll
    for (int jj = 0; jj < 8; jj++) { csum[jj] = 0.f; csq[jj] = 0.f; }

    #pragma unroll
    for (int i = 0; i < 8; i++) {
        int r = (i < 4) ? (ty * 4 + i) : (64 + ty * 4 + (i - 4));
        int gr = row0 + r;
        if (gr < NN) {
            float v[8];
            #pragma unroll
            for (int jj = 0; jj < 8; jj++) {
                float t = acc[i][jj] + bvals[jj];
                t = (t >= 0.f) ? t : SLOPE * t;
                v[jj] = t;
                csum[jj] += t;
                csq[jj]  += t * t;
            }
            float4 lo = make_float4(v[0], v[1], v[2], v[3]);
            float4 hi = make_float4(v[4], v[5], v[6], v[7]);
            *(float4*)&out[gr * H + tx * 4]      = lo;
            *(float4*)&out[gr * H + 64 + tx * 4] = hi;
        }
    }

    #pragma unroll
    for (int jj = 0; jj < 8; jj++) {
        atomicAdd(&s_sum[cols[jj]],   csum[jj]);
        atomicAdd(&s_sumsq[cols[jj]], csq[jj]);
    }
    __syncthreads();
    if (tid < H) {
        atomicAdd(&g_sum[tid],   s_sum[tid]);
        atomicAdd(&g_sumsq[tid], s_sumsq[tid]);
    }
}

// ---------------- BN ------------------------------------------------------
__global__ void k_bnprep(const float* __restrict__ gamma,
                         const float* __restrict__ beta) {
    int c = threadIdx.x;
    if (c < H) {
        float inv_n = 1.0f / (float)NN;
        float mu  = g_sum[c] * inv_n;
        float var = g_sumsq[c] * inv_n - mu * mu;
        float sc  = rsqrtf(var + BN_EPS) * gamma[c];
        g_scale[c] = sc;
        g_shift[c] = beta[c] - mu * sc;
    }
}

// BN apply: in-place on buffer `src` unless dout != nullptr (final layer)
__global__ void k_bn(int src, float* __restrict__ dout) {
    int i = blockIdx.x * blockDim.x + threadIdx.x;
    if (i < NN * 32) {
        const float* in = pick_w(src);
        float* outp = dout ? dout : pick_w(src);
        int c = (i & 31) * 4;
        float4 v = ((const float4*)in)[i];
        v.x = v.x * g_scale[c + 0] + g_shift[c + 0];
        v.y = v.y * g_scale[c + 1] + g_shift[c + 1];
        v.z = v.z * g_scale[c + 2] + g_shift[c + 2];
        v.w = v.w * g_scale[c + 3] + g_shift[c + 3];
        ((float4*)outp)[i] = v;
    }
}

// ---------------- launch ---------------------------------------------------
extern "C" void kernel_launch(void* const* d_in, const int* in_sizes, int n_in,
                              void* d_out, int out_size) {
    const float* x     = (const float*)d_in[0];
    const void*  ei    = d_in[1];                 // int32 or int64, detected on device
    const float* Wl    = (const float*)d_in[2];
    const float* bl    = (const float*)d_in[3];
    const float* Wr    = (const float*)d_in[4];
    const float* gamma = (const float*)d_in[5];
    const float* beta  = (const float*)d_in[6];
    float*       out   = (float*)d_out;

    // CSR build (every call; deterministic, cheap)
    k_detect  <<<1, 256>>>(ei);
    k_zero_deg<<<(NN + 255) / 256, 256>>>();
    k_hist    <<<(EE + 255) / 256, 256>>>(ei);
    k_scan    <<<1, 1024>>>();
    k_fill    <<<(EE + 255) / 256, 256>>>(ei);

    // layer l: input selector src_l, output buffer dst_l (1=A, 2=B)
    // l0: x->A, l1: A->B, l2: B->A, l3: A->B, BN of l3 -> d_out
    const int srcs[4] = {0, 1, 2, 1};
    const int dsts[4] = {1, 2, 1, 2};

    for (int l = 0; l < 4; l++) {
        k_agg<<<(NN + 7) / 8, 256>>>(x, srcs[l]);
        k_zero_stats<<<1, 128>>>();
        k_gemm<<<(NN + 127) / 128, 256>>>(x, srcs[l], dsts[l],
                                          Wl + l * H * H, Wr + l * H * H,
                                          bl + l * H);
        k_bnprep<<<1, 128>>>(gamma + l * H, beta + l * H);
        k_bn<<<(NN * 32 + 255) / 256, 256>>>(dsts[l], (l == 3) ? out : nullptr);
    }
}

// round 6
// speedup vs baseline: 1.3363x; 1.3363x over previous
#include <cuda_runtime.h>
#include <cuda_bf16.h>
#include <cstdint>

#define NN 50000
#define EE 800000
#define H  128
constexpr float BN_EPS = 1e-5f;
constexpr float SLOPE  = 0.01f;

// ---------------- scratch (device globals; no allocation allowed) ----------
// packed (bf16 hi | bf16 lo<<16) feature buffers
__device__ __align__(16) unsigned g_xP  [NN * H];
__device__ __align__(16) unsigned g_hA  [NN * H];
__device__ __align__(16) unsigned g_hB  [NN * H];
__device__ __align__(16) unsigned g_aggP[NN * H];
__device__ __align__(16) unsigned g_WtP [H * 256];   // W^T packed, per-layer
__device__ __align__(16) float    g_y   [NN * H];    // fp32 pre-BN activations
__device__ int   g_rowptr[NN + 1];
__device__ int   g_cursor[NN];
__device__ int   g_col[EE];
__device__ int   g_bsum[256];
__device__ int   g_boff[256];
__device__ float g_sum[H];
__device__ float g_sumsq[H];
__device__ float g_scale[H];
__device__ float g_shift[H];
__device__ int   g_is64;

// ---------------- helpers --------------------------------------------------
__device__ __forceinline__ const unsigned* pickP(int s) {
    return (s == 0) ? (const unsigned*)g_xP
         : (s == 1) ? (const unsigned*)g_hA : (const unsigned*)g_hB;
}
__device__ __forceinline__ unsigned* pickPw(int s) {
    return (s == 1) ? (unsigned*)g_hA : (unsigned*)g_hB;
}

__device__ __forceinline__ unsigned pack_f32(float v) {
    unsigned hb = (unsigned)__bfloat16_as_ushort(__float2bfloat16(v));
    float hf = __uint_as_float(hb << 16);
    float r = v - hf;
    unsigned lb = (unsigned)__bfloat16_as_ushort(__float2bfloat16(r));
    return hb | (lb << 16);
}
__device__ __forceinline__ float unpack_f32(unsigned p) {
    return __uint_as_float(p << 16) + __uint_as_float(p & 0xFFFF0000u);
}

__device__ __forceinline__ uint32_t smem_to_u32(const void* p) {
    uint32_t a;
    asm("{ .reg .u64 t; cvta.to.shared.u64 t, %1; cvt.u32.u64 %0, t; }"
        : "=r"(a) : "l"(p));
    return a;
}

// ldmatrix x4 (baseline PTX, legal on compute_103)
__device__ __forceinline__ void ldm_x4(uint32_t* f, uint32_t addr) {
    asm volatile("ldmatrix.sync.aligned.m8n8.x4.shared.b16 {%0,%1,%2,%3}, [%4];"
                 : "=r"(f[0]), "=r"(f[1]), "=r"(f[2]), "=r"(f[3]) : "r"(addr));
}
// mma m16n8k16 bf16 (baseline PTX, sm_80+)
__device__ __forceinline__ void mma_bf16(float* c, const uint32_t* a, const uint32_t* b) {
    asm volatile("mma.sync.aligned.m16n8k16.row.col.f32.bf16.bf16.f32 "
                 "{%0,%1,%2,%3}, {%4,%5,%6,%7}, {%8,%9}, {%0,%1,%2,%3};"
                 : "+f"(c[0]), "+f"(c[1]), "+f"(c[2]), "+f"(c[3])
                 : "r"(a[0]), "r"(a[1]), "r"(a[2]), "r"(a[3]),
                   "r"(b[0]), "r"(b[1]));
}

// edge accessors honoring detected dtype
__device__ __forceinline__ int edge_src(const void* ei, int e) {
    if (g_is64) return (int)((const long long*)ei)[e];
    return ((const int*)ei)[e];
}
__device__ __forceinline__ int edge_dst(const void* ei, int e) {
    if (g_is64) return (int)((const long long*)ei)[EE + e];
    return ((const int*)ei)[EE + e];
}

// ---------------- dtype detection -----------------------------------------
__global__ void k_detect(const void* ei) {
    __shared__ int bad;
    if (threadIdx.x == 0) bad = 0;
    __syncthreads();
    const long long* p = (const long long*)ei;
    long long v = p[threadIdx.x];
    if (v < 0 || v >= NN) atomicOr(&bad, 1);
    __syncthreads();
    if (threadIdx.x == 0) g_is64 = bad ? 0 : 1;
}

// ---------------- CSR build ------------------------------------------------
__global__ void k_zero_deg() {
    int i = blockIdx.x * blockDim.x + threadIdx.x;
    if (i < NN) g_cursor[i] = 0;
}
__global__ void k_hist(const void* __restrict__ ei) {
    int e = blockIdx.x * blockDim.x + threadIdx.x;
    if (e < EE) atomicAdd(&g_cursor[edge_dst(ei, e)], 1);
}
__global__ void k_scan1() {
    __shared__ int s[256];
    int t = threadIdx.x, i = blockIdx.x * 256 + t;
    int d = (i < NN) ? g_cursor[i] : 0;
    s[t] = d;
    __syncthreads();
    for (int off = 1; off < 256; off <<= 1) {
        int add = (t >= off) ? s[t - off] : 0;
        __syncthreads();
        s[t] += add;
        __syncthreads();
    }
    if (i < NN) g_rowptr[i] = s[t] - d;
    if (t == 255) g_bsum[blockIdx.x] = s[255];
}
__global__ void k_scan2() {
    __shared__ int s[256];
    int t = threadIdx.x;
    int d = (t < 196) ? g_bsum[t] : 0;
    s[t] = d;
    __syncthreads();
    for (int off = 1; off < 256; off <<= 1) {
        int add = (t >= off) ? s[t - off] : 0;
        __syncthreads();
        s[t] += add;
        __syncthreads();
    }
    if (t < 196) g_boff[t] = s[t] - d;
}
__global__ void k_scan3() {
    int i = blockIdx.x * 256 + threadIdx.x;
    if (i < NN) {
        int v = g_rowptr[i] + g_boff[blockIdx.x];
        g_rowptr[i] = v;
        g_cursor[i] = v;
    }
    if (i == 0) g_rowptr[NN] = EE;
}
__global__ void k_fill(const void* __restrict__ ei) {
    int e = blockIdx.x * blockDim.x + threadIdx.x;
    if (e < EE) {
        int src = edge_src(ei, e);
        int pos = atomicAdd(&g_cursor[edge_dst(ei, e)], 1);
        g_col[pos] = src;
    }
}

// ---------------- input / weight packing -----------------------------------
__global__ void k_xprep(const float* __restrict__ x) {
    int i = blockIdx.x * blockDim.x + threadIdx.x;
    if (i < NN * H) g_xP[i] = pack_f32(x[i]);
}
// W^T packed (B[n][k] = Wcat[k][n]); also zeroes BN stats
__global__ void k_wprep(const float* __restrict__ Wl, const float* __restrict__ Wr) {
    int idx = blockIdx.x * 256 + threadIdx.x;       // 32768
    int n = idx >> 8, k = idx & 255;
    float w = (k < H) ? Wl[k * H + n] : Wr[(k - H) * H + n];
    g_WtP[n * 256 + k] = pack_f32(w);
    if (blockIdx.x == 0 && threadIdx.x < H) {
        g_sum[threadIdx.x] = 0.f;
        g_sumsq[threadIdx.x] = 0.f;
    }
}

// ---------------- aggregation: one warp per node, packed uint4 lanes -------
__global__ void __launch_bounds__(256) k_agg(int src) {
    int warp = threadIdx.x >> 5;
    int lane = threadIdx.x & 31;
    int node = blockIdx.x * 8 + warp;
    if (node >= NN) return;
    const uint4* in4 = (const uint4*)pickP(src);
    int beg = g_rowptr[node];
    int end = g_rowptr[node + 1];
    float4 a = make_float4(0.f, 0.f, 0.f, 0.f);
    int j = beg;
    for (; j + 3 < end; j += 4) {
        int s0 = g_col[j + 0], s1 = g_col[j + 1];
        int s2 = g_col[j + 2], s3 = g_col[j + 3];
        uint4 w0 = in4[s0 * 32 + lane];
        uint4 w1 = in4[s1 * 32 + lane];
        uint4 w2 = in4[s2 * 32 + lane];
        uint4 w3 = in4[s3 * 32 + lane];
        a.x += (unpack_f32(w0.x) + unpack_f32(w1.x)) + (unpack_f32(w2.x) + unpack_f32(w3.x));
        a.y += (unpack_f32(w0.y) + unpack_f32(w1.y)) + (unpack_f32(w2.y) + unpack_f32(w3.y));
        a.z += (unpack_f32(w0.z) + unpack_f32(w1.z)) + (unpack_f32(w2.z) + unpack_f32(w3.z));
        a.w += (unpack_f32(w0.w) + unpack_f32(w1.w)) + (unpack_f32(w2.w) + unpack_f32(w3.w));
    }
    for (; j < end; j++) {
        uint4 w0 = in4[g_col[j] * 32 + lane];
        a.x += unpack_f32(w0.x); a.y += unpack_f32(w0.y);
        a.z += unpack_f32(w0.z); a.w += unpack_f32(w0.w);
    }
    float inv = 1.0f / (float)max(end - beg, 1);
    uint4 o = make_uint4(pack_f32(a.x * inv), pack_f32(a.y * inv),
                         pack_f32(a.z * inv), pack_f32(a.w * inv));
    ((uint4*)g_aggP)[node * 32 + lane] = o;
}

// ---------------- tensor-core GEMM (mma.sync bf16, 3-term split) -----------
// D[128,128] fp32 = sum over K=256 of Ah@Bh + Ah@Bl + Al@Bh
// A = [agg | h], B = W^T[n][k]. Epilogue: bias + leaky_relu -> g_y.
// smem tiles: 128 rows x 64 bf16, row stride 72 bf16 (144B; ldmatrix
// conflict-free: banks 4r mod 32 with 16B-group shifts all distinct).
#define SA_STRIDE 144
#define TILE_BYTES (128 * SA_STRIDE)           // 18432
#define GEMM_SMEM  (4 * TILE_BYTES)            // 73728

__device__ __forceinline__ void load_split_tile(
    uint32_t sm_hi, uint32_t sm_lo,
    const unsigned* __restrict__ src, int row0, int stride, int col0,
    int tid, int rows_valid)
{
    int r = tid >> 1;
    int h = (tid & 1) * 32;
    bool valid = r < rows_valid;
    const uint4* p4 = (const uint4*)(src + (size_t)(row0 + r) * stride + col0 + h);
    #pragma unroll
    for (int u = 0; u < 8; u++) {
        uint4 w = valid ? p4[u] : make_uint4(0u, 0u, 0u, 0u);
        unsigned h01 = __byte_perm(w.x, w.y, 0x5410);   // hi bf16 pair
        unsigned h23 = __byte_perm(w.z, w.w, 0x5410);
        unsigned l01 = __byte_perm(w.x, w.y, 0x7632);   // lo bf16 pair
        unsigned l23 = __byte_perm(w.z, w.w, 0x7632);
        uint32_t off = (uint32_t)(r * SA_STRIDE + (h + u * 4) * 2);
        asm volatile("st.shared.v2.b32 [%0], {%1,%2};"
                     :: "r"(sm_hi + off), "r"(h01), "r"(h23) : "memory");
        asm volatile("st.shared.v2.b32 [%0], {%1,%2};"
                     :: "r"(sm_lo + off), "r"(l01), "r"(l23) : "memory");
    }
}

__global__ void __launch_bounds__(256, 1) k_gemm(int src, const float* __restrict__ bias) {
    extern __shared__ char smem[];
    uint32_t sAh = smem_to_u32(smem);
    uint32_t sAl = sAh + TILE_BYTES;
    uint32_t sBh = sAh + 2 * TILE_BYTES;
    uint32_t sBl = sAh + 3 * TILE_BYTES;

    const int tid  = threadIdx.x;
    const int lane = tid & 31;
    const int wid  = tid >> 5;
    const int wm   = wid >> 1;       // 0..3  (m: 32 rows each)
    const int wn   = wid & 1;        // 0..1  (n: 64 cols each)
    const int row0 = blockIdx.x * 128;
    const unsigned* hsrc = pickP(src);

    int arows = NN - row0;
    if (arows > 128) arows = 128;

    float acc[2][8][4];
    #pragma unroll
    for (int i = 0; i < 2; i++)
        #pragma unroll
        for (int j = 0; j < 8; j++)
            #pragma unroll
            for (int q = 0; q < 4; q++) acc[i][j][q] = 0.f;

    const int lrow = lane & 15;
    const int lchk = lane >> 4;

    for (int c = 0; c < 4; c++) {
        const unsigned* asrc = (c < 2) ? (const unsigned*)g_aggP : hsrc;
        int acol = (c & 1) * 64;
        load_split_tile(sAh, sAl, asrc, row0, 128, acol, tid, arows);
        load_split_tile(sBh, sBl, (const unsigned*)g_WtP, 0, 256, c * 64, tid, 128);
        __syncthreads();

        #pragma unroll
        for (int ks = 0; ks < 4; ks++) {
            uint32_t Ah[2][4], Al[2][4];
            #pragma unroll
            for (int im = 0; im < 2; im++) {
                uint32_t aoff = (uint32_t)((wm * 32 + im * 16 + lrow) * SA_STRIDE
                                           + (ks * 16 + lchk * 8) * 2);
                ldm_x4(Ah[im], sAh + aoff);
                ldm_x4(Al[im], sAl + aoff);
            }
            uint32_t Bh[8][2], Bl[8][2];
            #pragma unroll
            for (int jn = 0; jn < 4; jn++) {
                uint32_t boff = (uint32_t)((wn * 64 + jn * 16 + lrow) * SA_STRIDE
                                           + (ks * 16 + lchk * 8) * 2);
                uint32_t t[4];
                ldm_x4(t, sBh + boff);
                Bh[2 * jn][0] = t[0]; Bh[2 * jn][1] = t[2];
                Bh[2 * jn + 1][0] = t[1]; Bh[2 * jn + 1][1] = t[3];
                ldm_x4(t, sBl + boff);
                Bl[2 * jn][0] = t[0]; Bl[2 * jn][1] = t[2];
                Bl[2 * jn + 1][0] = t[1]; Bl[2 * jn + 1][1] = t[3];
            }
            #pragma unroll
            for (int im = 0; im < 2; im++)
                #pragma unroll
                for (int j = 0; j < 8; j++)
                    mma_bf16(acc[im][j], Ah[im], Bh[j]);
            #pragma unroll
            for (int im = 0; im < 2; im++)
                #pragma unroll
                for (int j = 0; j < 8; j++)
                    mma_bf16(acc[im][j], Ah[im], Bl[j]);
            #pragma unroll
            for (int im = 0; im < 2; im++)
                #pragma unroll
                for (int j = 0; j < 8; j++)
                    mma_bf16(acc[im][j], Al[im], Bh[j]);
        }
        __syncthreads();
    }

    // epilogue: bias + leaky relu -> g_y
    const int lr  = lane >> 2;
    const int lc2 = (lane & 3) * 2;
    #pragma unroll
    for (int im = 0; im < 2; im++) {
        #pragma unroll
        for (int j = 0; j < 8; j++) {
            int n = wn * 64 + j * 8 + lc2;
            float b0 = bias[n], b1 = bias[n + 1];
            int m0 = row0 + wm * 32 + im * 16 + lr;
            if (m0 < NN) {
                float v0 = acc[im][j][0] + b0;
                float v1 = acc[im][j][1] + b1;
                v0 = (v0 >= 0.f) ? v0 : SLOPE * v0;
                v1 = (v1 >= 0.f) ? v1 : SLOPE * v1;
                *(float2*)&g_y[(size_t)m0 * H + n] = make_float2(v0, v1);
            }
            int m1 = m0 + 8;
            if (m1 < NN) {
                float v2 = acc[im][j][2] + b0;
                float v3 = acc[im][j][3] + b1;
                v2 = (v2 >= 0.f) ? v2 : SLOPE * v2;
                v3 = (v3 >= 0.f) ? v3 : SLOPE * v3;
                *(float2*)&g_y[(size_t)m1 * H + n] = make_float2(v2, v3);
            }
        }
    }
}

// ---------------- BN stats / prep / apply ----------------------------------
__global__ void k_stats() {
    int t = threadIdx.x;            // 128 threads = columns
    int r0 = blockIdx.x * 250;      // 200 blocks x 250 rows
    float s = 0.f, q = 0.f;
    for (int r = 0; r < 250; r++) {
        float v = g_y[(size_t)(r0 + r) * H + t];
        s += v;
        q += v * v;
    }
    atomicAdd(&g_sum[t], s);
    atomicAdd(&g_sumsq[t], q);
}
__global__ void k_bnprep(const float* __restrict__ gamma,
                         const float* __restrict__ beta) {
    int c = threadIdx.x;
    if (c < H) {
        float inv_n = 1.0f / (float)NN;
        float mu  = g_sum[c] * inv_n;
        float var = g_sumsq[c] * inv_n - mu * mu;
        float sc  = rsqrtf(var + BN_EPS) * gamma[c];
        g_scale[c] = sc;
        g_shift[c] = beta[c] - mu * sc;
    }
}
// BN apply: g_y -> packed h buffer dst; final layer also writes fp32 dout
__global__ void k_bn(int dst, float* __restrict__ dout) {
    int i = blockIdx.x * blockDim.x + threadIdx.x;
    if (i < NN * 32) {
        int c = (i & 31) * 4;
        float4 v = ((const float4*)g_y)[i];
        v.x = v.x * g_scale[c + 0] + g_shift[c + 0];
        v.y = v.y * g_scale[c + 1] + g_shift[c + 1];
        v.z = v.z * g_scale[c + 2] + g_shift[c + 2];
        v.w = v.w * g_scale[c + 3] + g_shift[c + 3];
        uint4 p = make_uint4(pack_f32(v.x), pack_f32(v.y), pack_f32(v.z), pack_f32(v.w));
        ((uint4*)pickPw(dst))[i] = p;
        if (dout) ((float4*)dout)[i] = v;
    }
}

// ---------------- launch ---------------------------------------------------
extern "C" void kernel_launch(void* const* d_in, const int* in_sizes, int n_in,
                              void* d_out, int out_size) {
    const float* x     = (const float*)d_in[0];
    const void*  ei    = d_in[1];
    const float* Wl    = (const float*)d_in[2];
    const float* bl    = (const float*)d_in[3];
    const float* Wr    = (const float*)d_in[4];
    const float* gamma = (const float*)d_in[5];
    const float* beta  = (const float*)d_in[6];
    float*       out   = (float*)d_out;

    cudaFuncSetAttribute(k_gemm, cudaFuncAttributeMaxDynamicSharedMemorySize, GEMM_SMEM);

    // CSR build
    k_detect  <<<1, 256>>>(ei);
    k_zero_deg<<<196, 256>>>();
    k_hist    <<<(EE + 255) / 256, 256>>>(ei);
    k_scan1   <<<196, 256>>>();
    k_scan2   <<<1, 256>>>();
    k_scan3   <<<196, 256>>>();
    k_fill    <<<(EE + 255) / 256, 256>>>(ei);
    k_xprep   <<<(NN * H + 255) / 256, 256>>>(x);

    // l0: xP->A, l1: A->B, l2: B->A, l3: A->B (+ d_out)
    const int srcs[4] = {0, 1, 2, 1};
    const int dsts[4] = {1, 2, 1, 2};

    for (int l = 0; l < 4; l++) {
        k_agg  <<<(NN + 7) / 8, 256>>>(srcs[l]);
        k_wprep<<<128, 256>>>(Wl + l * H * H, Wr + l * H * H);
        k_gemm <<<(NN + 127) / 128, 256, GEMM_SMEM>>>(srcs[l], bl + l * H);
        k_stats<<<200, 128>>>();
        k_bnprep<<<1, 128>>>(gamma + l * H, beta + l * H);
        k_bn   <<<(NN * 32 + 255) / 256, 256>>>(dsts[l], (l == 3) ? out : nullptr);
    }
}